// round 6
// baseline (speedup 1.0000x reference)
#include <cuda_runtime.h>
#include <cstdint>
#include <cstddef>

// Problem sizes (fixed by the reference)
#define HH     256
#define G4     1024
#define BB     256
#define TT     512
#define DD     64
#define NCLASS 10

// Recurrent kernel config
#define CS   8     // CTAs per cluster
#define NC   16    // clusters -> 128 CTAs, 1 per SM
#define BC   16    // batch rows per cluster
#define GJ   32    // hidden (j) columns per CTA
#define RTH  512   // threads per CTA -> 4 warps per SMSP
#define HPAD 264   // padded row stride, H-wide smem rows (floats)
#define DPAD 72    // padded row stride, D-wide smem rows (floats)
#define WGS  (GJ * HPAD + 8)   // gate stride in Ws  (+8 floats: bank de-alias, 64B mod 128)
#define WIGS (GJ * DPAD + 8)   // gate stride in Wis

// Shared layout (floats)
#define WS_OFF   0                          // W_hh slices: [4][WGS]
#define WIS_OFF  (4 * WGS)                  // W_ih slices: [4][WIGS]
#define HS_OFF   (WIS_OFF + 4 * WIGS)       // h tile:      [BC][HPAD]
#define XS_OFF   (HS_OFF + BC * HPAD)       // x tiles:     [2][BC][DPAD]
#define REC_SMEM ((XS_OFF + 2 * BC * DPAD) * 4)

// Global state: double-buffered hidden state (c stays in registers)
__device__ float g_h[2][BB * HH];

__device__ __forceinline__ float sigm(float x) {
    return 1.0f / (1.0f + __expf(-x));
}
__device__ __forceinline__ float tanh_fast(float x) {
    return 1.0f - 2.0f / (__expf(2.0f * x) + 1.0f);
}

// Packed dual-fp32 FMA (SASS FFMA2)
#define PFMA(acc, A, B) \
    asm("fma.rn.f32x2 %0, %1, %2, %0;" : "+l"(acc) : "l"(A), "l"(B))
#define ACCP(gg, i, W, V)                 \
    do {                                  \
        PFMA(acc2[gg][i], (W).x, (V).x);  \
        PFMA(acc2[gg][i], (W).y, (V).y);  \
    } while (0)

// ---------------------------------------------------------------------------
// Single fused persistent kernel: h0-zero + 512-step recurrence + output head.
// Cluster q owns batch rows [q*BC,(q+1)*BC). CTA rank r owns hidden cols
// [r*GJ,(r+1)*GJ).
// tid = jl*16 + gh*8 + bgrp*2 + kh :
//   jl in [0,32): hidden col;  gh in {0,1}: gate pair (i,f | g,o);
//   bgrp in [0,4): base batch lane;  kh in {0,1}: k-half.
// acc2[gg][i]: packed partials for gate 2*gh+gg, batch row bgrp+4*i, this k-half.
// Reduce: shfl_xor(1) over kh, then shfl_xor(8) exchanges gate pairs so each
// thread ends with all 4 gates for its single owned row bl = bgrp + 4*(2*gh+kh).
// ---------------------------------------------------------------------------
__global__ __launch_bounds__(RTH, 1) __cluster_dims__(CS, 1, 1)
void lstm_kernel(const float* __restrict__ x,
                 const float* __restrict__ Wih,
                 const float* __restrict__ Whh,
                 const float* __restrict__ bih,
                 const float* __restrict__ bhh,
                 const float* __restrict__ Wout,
                 const float* __restrict__ bout,
                 float* __restrict__ out) {
    extern __shared__ float sm[];
    float* Ws  = sm + WS_OFF;
    float* Wis = sm + WIS_OFF;
    float* hs  = sm + HS_OFF;
    float* xs  = sm + XS_OFF;       // two slots of BC*DPAD

    const int cta  = blockIdx.x;
    const int q    = cta / CS;
    const int r    = cta % CS;
    const int tid  = threadIdx.x;
    const int jl   = tid >> 4;          // [0,32)
    const int gh   = (tid >> 3) & 1;    // {0,1}
    const int bgrp = (tid >> 1) & 3;    // [0,4)
    const int kh   = tid & 1;           // {0,1}
    const int jg   = r * GJ + jl;

    // ---- zero this CTA's slice of h[0] ----
    {
        int bl = tid >> 5, c = tid & 31;          // 512 = 16 rows x 32 cols
        g_h[0][(q * BC + bl) * HH + r * GJ + c] = 0.0f;
    }

    // ---- one-time weight loads (gate rows with +8-float gap) ----
    for (int f = tid; f < 128 * 64; f += RTH) {
        int row = f >> 6, c4 = (f & 63) << 2;
        int g = row >> 5, j2 = row & 31;
        float4 v = *reinterpret_cast<const float4*>(
            &Whh[(size_t)(g * HH + r * GJ + j2) * HH + c4]);
        *reinterpret_cast<float4*>(&Ws[g * WGS + j2 * HPAD + c4]) = v;
    }
    for (int f = tid; f < 128 * 16; f += RTH) {
        int row = f >> 4, d4 = (f & 15) << 2;
        int g = row >> 5, j2 = row & 31;
        float4 v = *reinterpret_cast<const float4*>(
            &Wih[(size_t)(g * HH + r * GJ + j2) * DD + d4]);
        *reinterpret_cast<float4*>(&Wis[g * WIGS + j2 * DPAD + d4]) = v;
    }

    float biasv[4];
#pragma unroll
    for (int g = 0; g < 4; g++)
        biasv[g] = bih[g * HH + jg] + bhh[g * HH + jg];

    // owned batch row for the pointwise update
    const int bl = bgrp + 4 * (2 * gh + kh);
    const int bog = q * BC + bl;

    // x staging: first 256 threads handle the 16x64 tile
    const int xbl = (tid >> 4) & 15, xd4 = (tid & 15) << 2;
    const bool xldr = (tid < 256);
    const float* xbase = &x[(size_t)(q * BC + xbl) * TT * DD + xd4];
    float4 xreg = make_float4(0.f, 0.f, 0.f, 0.f);
    if (xldr) {
        *reinterpret_cast<float4*>(&xs[xbl * DPAD + xd4]) =
            *reinterpret_cast<const float4*>(xbase);
        xreg = *reinterpret_cast<const float4*>(xbase + DD);
    }

    // hot-loop base pointers
    const float* wp0  = Ws  + 2 * gh * WGS  + jl * HPAD + kh * 4;
    const float* wip0 = Wis + 2 * gh * WIGS + jl * DPAD + kh * 4;

    float cstate = 0.0f;
    __syncthreads();   // weights + xs slot0 ready (CTA-local)
    asm volatile("barrier.cluster.arrive.aligned;" ::: "memory");  // release h0

    for (int t = 0; t < TT; t++) {
        unsigned long long acc2[2][4];
#pragma unroll
        for (int gg = 0; gg < 2; gg++)
#pragma unroll
            for (int i = 0; i < 4; i++) acc2[gg][i] = 0ull;

        const float* xp = xs + (t & 1) * BC * DPAD + bgrp * DPAD + kh * 4;

        // ---- input projection part A (hides cluster barrier skew) ----
#pragma unroll
        for (int cc = 0; cc < 4; cc++) {
            int d = cc * 8;
            ulonglong2 w0 = *reinterpret_cast<const ulonglong2*>(&wip0[d]);
            ulonglong2 w1 = *reinterpret_cast<const ulonglong2*>(&wip0[d + WIGS]);
            ulonglong2 v0 = *reinterpret_cast<const ulonglong2*>(&xp[d + 0 * DPAD]);
            ulonglong2 v1 = *reinterpret_cast<const ulonglong2*>(&xp[d + 4 * DPAD]);
            ulonglong2 v2 = *reinterpret_cast<const ulonglong2*>(&xp[d + 8 * DPAD]);
            ulonglong2 v3 = *reinterpret_cast<const ulonglong2*>(&xp[d + 12 * DPAD]);
            ACCP(0,0,w0,v0); ACCP(0,1,w0,v1); ACCP(0,2,w0,v2); ACCP(0,3,w0,v3);
            ACCP(1,0,w1,v0); ACCP(1,1,w1,v1); ACCP(1,2,w1,v2); ACCP(1,3,w1,v3);
        }

        // ---- h(t-1) published by all peer CTAs ----
        asm volatile("barrier.cluster.wait.aligned;" ::: "memory");

        const float* hsrc = g_h[t & 1];
        float* hdst = g_h[(t + 1) & 1];

        // issue h-tile loads NOW; latency hidden by input-proj part B
        float4 hreg[2];
#pragma unroll
        for (int ii = 0; ii < 2; ii++) {
            int f = tid + RTH * ii;            // [0,1024)
            int hbl = f >> 6, c4 = (f & 63) << 2;
            hreg[ii] = __ldcg(reinterpret_cast<const float4*>(
                &hsrc[(q * BC + hbl) * HH + c4]));
        }

        // ---- input projection part B ----
#pragma unroll
        for (int cc = 4; cc < 8; cc++) {
            int d = cc * 8;
            ulonglong2 w0 = *reinterpret_cast<const ulonglong2*>(&wip0[d]);
            ulonglong2 w1 = *reinterpret_cast<const ulonglong2*>(&wip0[d + WIGS]);
            ulonglong2 v0 = *reinterpret_cast<const ulonglong2*>(&xp[d + 0 * DPAD]);
            ulonglong2 v1 = *reinterpret_cast<const ulonglong2*>(&xp[d + 4 * DPAD]);
            ulonglong2 v2 = *reinterpret_cast<const ulonglong2*>(&xp[d + 8 * DPAD]);
            ulonglong2 v3 = *reinterpret_cast<const ulonglong2*>(&xp[d + 12 * DPAD]);
            ACCP(0,0,w0,v0); ACCP(0,1,w0,v1); ACCP(0,2,w0,v2); ACCP(0,3,w0,v3);
            ACCP(1,0,w1,v0); ACCP(1,1,w1,v1); ACCP(1,2,w1,v2); ACCP(1,3,w1,v3);
        }

        // publish x(t+1) into the other slot; prefetch x(t+2)
        if (xldr && t + 1 < TT) {
            *reinterpret_cast<float4*>(
                &xs[((t + 1) & 1) * BC * DPAD + xbl * DPAD + xd4]) = xreg;
            if (t + 2 < TT)
                xreg = *reinterpret_cast<const float4*>(xbase + (size_t)(t + 2) * DD);
        }

        // stage h tile into shared
#pragma unroll
        for (int ii = 0; ii < 2; ii++) {
            int f = tid + RTH * ii;
            int hbl = f >> 6, c4 = (f & 63) << 2;
            *reinterpret_cast<float4*>(&hs[hbl * HPAD + c4]) = hreg[ii];
        }
        __syncthreads();   // hs + xs(t+1) ready

        // ---- recurrent part: k over H=256, this thread's half ----
        {
            const float* hp = hs + bgrp * HPAD + kh * 4;
#pragma unroll 2
            for (int cc = 0; cc < 32; cc++) {
                int k = cc * 8;
                ulonglong2 w0 = *reinterpret_cast<const ulonglong2*>(&wp0[k]);
                ulonglong2 w1 = *reinterpret_cast<const ulonglong2*>(&wp0[k + WGS]);
                ulonglong2 v0 = *reinterpret_cast<const ulonglong2*>(&hp[k + 0 * HPAD]);
                ulonglong2 v1 = *reinterpret_cast<const ulonglong2*>(&hp[k + 4 * HPAD]);
                ulonglong2 v2 = *reinterpret_cast<const ulonglong2*>(&hp[k + 8 * HPAD]);
                ulonglong2 v3 = *reinterpret_cast<const ulonglong2*>(&hp[k + 12 * HPAD]);
                ACCP(0,0,w0,v0); ACCP(0,1,w0,v1); ACCP(0,2,w0,v2); ACCP(0,3,w0,v3);
                ACCP(1,0,w1,v0); ACCP(1,1,w1,v1); ACCP(1,2,w1,v2); ACCP(1,3,w1,v3);
            }
        }

        // ---- reduce: unpack + kh pair-sum, then gate-pair exchange (xor 8) ----
        float red[2][4];
#pragma unroll
        for (int gg = 0; gg < 2; gg++)
#pragma unroll
            for (int i = 0; i < 4; i++) {
                float lo = __uint_as_float((unsigned)acc2[gg][i]);
                float hi = __uint_as_float((unsigned)(acc2[gg][i] >> 32));
                float a = lo + hi;
                red[gg][i] = a + __shfl_xor_sync(0xffffffffu, a, 1);
            }

        float mine[2], oth[2];
#pragma unroll
        for (int gg = 0; gg < 2; gg++) {
            // send my gate-pair sums for the partner's rows; receive theirs for mine
            float send = gh ? (kh ? red[gg][1] : red[gg][0])
                            : (kh ? red[gg][3] : red[gg][2]);
            oth[gg]  = __shfl_xor_sync(0xffffffffu, send, 8);
            mine[gg] = gh ? (kh ? red[gg][3] : red[gg][2])
                          : (kh ? red[gg][1] : red[gg][0]);
        }
        // assemble gates i,f,g,o for owned row
        float zi = (gh ? oth[0]  : mine[0]) + biasv[0];
        float zf = (gh ? oth[1]  : mine[1]) + biasv[1];
        float zg = (gh ? mine[0] : oth[0])  + biasv[2];
        float zo = (gh ? mine[1] : oth[1])  + biasv[3];

        {
            float ig = sigm(zi), fg = sigm(zf);
            float gg2 = tanh_fast(zg), og = sigm(zo);
            cstate = fg * cstate + ig * gg2;
            __stcg(&hdst[bog * HH + jg], og * tanh_fast(cstate));
        }

        // release this step's h to the cluster
        asm volatile("barrier.cluster.arrive.aligned;" ::: "memory");
    }
    asm volatile("barrier.cluster.wait.aligned;" ::: "memory");

    // ---- output head: this CTA handles local batch rows {2r, 2r+1} ----
    // h_T = g_h[0] (TT even). 2 rows x 10 classes = 20 tasks over 16 warps.
    {
        const int w = tid >> 5, lane = tid & 31;
        for (int task = w; task < 2 * NCLASS; task += 16) {
            int row = task / NCLASS, cls = task % NCLASS;
            int b = q * BC + 2 * r + row;
            float s = 0.0f;
#pragma unroll
            for (int k = lane; k < HH; k += 32)
                s += __ldcg(&g_h[0][b * HH + k]) * Wout[cls * HH + k];
#pragma unroll
            for (int o = 16; o; o >>= 1) s += __shfl_xor_sync(0xffffffffu, s, o);
            if (lane == 0) out[b * NCLASS + cls] = sigm(s + bout[cls]);
        }
    }
}

extern "C" void kernel_launch(void* const* d_in, const int* in_sizes, int n_in,
                              void* d_out, int out_size) {
    const float* x    = (const float*)d_in[0];
    const float* Wih  = (const float*)d_in[1];
    const float* Whh  = (const float*)d_in[2];
    const float* bih  = (const float*)d_in[3];
    const float* bhh  = (const float*)d_in[4];
    const float* Wout = (const float*)d_in[5];
    const float* bout = (const float*)d_in[6];
    float* out = (float*)d_out;

    cudaFuncSetAttribute(lstm_kernel,
                         cudaFuncAttributeMaxDynamicSharedMemorySize, REC_SMEM);

    lstm_kernel<<<NC * CS, RTH, REC_SMEM>>>(x, Wih, Whh, bih, bhh,
                                            Wout, bout, out);
}

// round 9
// speedup vs baseline: 2.2183x; 2.2183x over previous
#include <cuda_runtime.h>
#include <cuda_fp16.h>
#include <cstdint>
#include <cstddef>

// Problem sizes
#define HH     256
#define BB     256
#define TT     512
#define DD     64
#define NCLASS 10

// Topology: 16 clusters x 8 CTAs; cluster owns 16 batch rows; CTA owns 32 j.
#define CS   8
#define NC   16
#define BC   16
#define RTH  256   // 8 warps
#define NKT  20    // k-tiles: 16 for H=256, 4 for D=64

// ---- SMEM layout (bytes) ----
// A-frags: [8 m-tiles][20 k-tiles][32 lanes][4 u32] = 81920 B each (hi, lo)
// B-frags: [20 kt][2 nt][32 lanes][2 u32] = 10240 B each (hi, lo)
// z:       [128 m][18 floats] = 9216 B
#define SM_AHI 0
#define SM_ALO (SM_AHI + 8 * NKT * 512)
#define SM_BHI (SM_ALO + 8 * NKT * 512)
#define SM_BLO (SM_BHI + NKT * 2 * 256)
#define SM_Z   (SM_BLO + NKT * 2 * 256)
#define SM_TOTAL (SM_Z + 128 * 18 * 4)   // 193536

// h exchange: B-fragment-layout image, words 0..2047 (16 h k-tiles), per parity.
__device__ uint32_t g_hfrag[2][NC][2][2048];   // [parity][cluster][hi/lo][word]
__device__ float g_hT[BB * HH];

// ---------------------------------------------------------------------------
__device__ __forceinline__ float sigm(float x) { return 1.0f / (1.0f + __expf(-x)); }
__device__ __forceinline__ float tanh_fast(float x) {
    return 1.0f - 2.0f / (__expf(2.0f * x) + 1.0f);
}
// fp16 hi/lo split of a pair -> packed words
__device__ __forceinline__ uint32_t split_pack(float a, float b, uint32_t& lo) {
    __half ah = __float2half_rn(a), bh = __float2half_rn(b);
    __half al = __float2half_rn(a - __half2float(ah));
    __half bl = __float2half_rn(b - __half2float(bh));
    __half2 h2 = __halves2half2(ah, bh), l2 = __halves2half2(al, bl);
    lo = *reinterpret_cast<uint32_t*>(&l2);
    return *reinterpret_cast<uint32_t*>(&h2);
}
__device__ __forceinline__ void mma16816(float* d, const uint32_t* a, const uint32_t* b) {
    asm volatile(
        "mma.sync.aligned.m16n8k16.row.col.f32.f16.f16.f32 "
        "{%0,%1,%2,%3}, {%4,%5,%6,%7}, {%8,%9}, {%0,%1,%2,%3};"
        : "+f"(d[0]), "+f"(d[1]), "+f"(d[2]), "+f"(d[3])
        : "r"(a[0]), "r"(a[1]), "r"(a[2]), "r"(a[3]), "r"(b[0]), "r"(b[1]));
}
#define CLU_ARRIVE() asm volatile("barrier.cluster.arrive.aligned;" ::: "memory")
#define CLU_WAIT()   asm volatile("barrier.cluster.wait.aligned;"   ::: "memory")

// ---------------------------------------------------------------------------
// Fragment layouts (PTX ISA m16n8k16):
//  A (row-major): lane l, reg j: row = 16*mt + (l>>2) + 8*(j&1),
//                 col = 16*kt + 2*(l&3) + 8*(j>>1)
//  B (col):       lane l, reg j: k = 16*kt + 2*(l&3) + 8*j (+0/+1 packed),
//                 n = nt*8 + (l>>2)
//  D:             lane l: rows 16*mt + (l>>2) (+8), cols 2*(l&3) (+1)
// A rows: m = gate*32 + jl (torch gate order i,f,g,o); k<256 -> Whh, else Wih.
// ---------------------------------------------------------------------------
__global__ __launch_bounds__(RTH, 1) __cluster_dims__(CS, 1, 1)
void lstm_kernel(const float* __restrict__ x,
                 const float* __restrict__ Wih,
                 const float* __restrict__ Whh,
                 const float* __restrict__ bih,
                 const float* __restrict__ bhh,
                 const float* __restrict__ Wout,
                 const float* __restrict__ bout,
                 float* __restrict__ out) {
    extern __shared__ __align__(16) char smc[];
    const int tid = threadIdx.x;
    const int wid = tid >> 5, lan = tid & 31;
    const int cta = blockIdx.x, q = cta / CS, r = cta % CS;

    uint32_t* Ahi = reinterpret_cast<uint32_t*>(smc + SM_AHI);
    uint32_t* Alo = reinterpret_cast<uint32_t*>(smc + SM_ALO);
    uint32_t* Bhi = reinterpret_cast<uint32_t*>(smc + SM_BHI);
    uint32_t* Blo = reinterpret_cast<uint32_t*>(smc + SM_BLO);
    float*    zb  = reinterpret_cast<float*>(smc + SM_Z);

    // ---- zero parity-0 h image (h0 = 0): 1024 uint4 per cluster, 128 per CTA ----
    if (tid < 128)
        reinterpret_cast<uint4*>(&g_hfrag[0][q][0][0])[r * 128 + tid] =
            make_uint4(0u, 0u, 0u, 0u);

    // ---- build A fragments (weights, hi/lo) : 20480 words, 80 per thread ----
#pragma unroll 1
    for (int i = 0; i < 80; i++) {
        int widx = tid + 256 * i;
        int mt  = widx / 2560;
        int rem = widx % 2560;
        int kt  = rem >> 7;
        int w2  = rem & 127;
        int l   = w2 >> 2, reg = w2 & 3;
        int m  = 16 * mt + (l >> 2) + 8 * (reg & 1);
        int kk = 16 * kt + 2 * (l & 3) + 8 * (reg >> 1);
        int row = (m >> 5) * HH + r * 32 + (m & 31);   // gate*256 + j
        float2 v;
        if (kk < HH)
            v = *reinterpret_cast<const float2*>(&Whh[(size_t)row * HH + kk]);
        else
            v = *reinterpret_cast<const float2*>(&Wih[(size_t)row * DD + (kk - HH)]);
        uint32_t lo, hi = split_pack(v.x, v.y, lo);
        Ahi[widx] = hi;
        Alo[widx] = lo;
    }

    // ---- pointwise constants: thread owns (jp = tid>>4, b = tid&15) ----
    const int jp = tid >> 4, bq = tid & 15;
    const int j0 = r * 32 + 2 * jp;
    float bz[8];
#pragma unroll
    for (int g = 0; g < 4; g++) {
        bz[2 * g + 0] = bih[g * HH + j0] + bhh[g * HH + j0];
        bz[2 * g + 1] = bih[g * HH + j0 + 1] + bhh[g * HH + j0 + 1];
    }
    // h-writer fragment word index for (j0,j0+1) x batch bq
    const int wkt = 2 * r + (jp >> 3);
    const int wnt = bq >> 3;
    const int wl  = (bq & 7) * 4 + (jp & 3);
    const int wreg = (jp >> 2) & 1;
    const int hwi = (wkt * 2 + wnt) * 64 + wl * 2 + wreg;

    // ---- x-frag ownership: words w0 = 2048 + 2*tid, w0+1 ----
    const int w0  = 2048 + 2 * tid;
    const int xkt = w0 >> 7;                 // 16..19
    const int xr2 = w0 & 127;
    const int xnt = xr2 >> 6;
    const int xl  = (xr2 >> 1) & 31;
    const int xn  = xnt * 8 + (xl >> 2);
    const int xd0 = (xkt - 16) * 16 + 2 * (xl & 3);
    const float* xrow = x + ((size_t)(q * BC + xn) * TT) * DD;
    float2 pva = *reinterpret_cast<const float2*>(xrow + 0 * DD + xd0);
    float2 pvb = *reinterpret_cast<const float2*>(xrow + 0 * DD + xd0 + 8);

    float cst[2] = {0.f, 0.f};

    __syncthreads();
    CLU_ARRIVE();   // publish zeroed h image

    for (int t = 0; t < TT; t++) {
        CLU_WAIT();   // h(t-1) frags from all peers visible; all our MMA reads done

        // ---- ingest h frags (pure copy, 512 uint4 each) ----
        {
            const uint4* ghi = reinterpret_cast<const uint4*>(&g_hfrag[t & 1][q][0][0]);
            const uint4* glo = reinterpret_cast<const uint4*>(&g_hfrag[t & 1][q][1][0]);
            uint4* shi = reinterpret_cast<uint4*>(Bhi);
            uint4* slo = reinterpret_cast<uint4*>(Blo);
            shi[tid]       = __ldcg(ghi + tid);
            shi[tid + 256] = __ldcg(ghi + tid + 256);
            slo[tid]       = __ldcg(glo + tid);
            slo[tid + 256] = __ldcg(glo + tid + 256);
        }
        // ---- x frags from prefetched regs ----
        {
            uint32_t lo0, hi0 = split_pack(pva.x, pva.y, lo0);
            uint32_t lo1, hi1 = split_pack(pvb.x, pvb.y, lo1);
            *reinterpret_cast<uint2*>(Bhi + w0) = make_uint2(hi0, hi1);
            *reinterpret_cast<uint2*>(Blo + w0) = make_uint2(lo0, lo1);
        }
        __syncthreads();   // fragments ready

        // ---- MMA: warp wid -> m-tile wid; 2 n-tiles; 20 k-tiles; 3 passes ----
        {
            float acc0[4] = {0.f, 0.f, 0.f, 0.f};
            float acc1[4] = {0.f, 0.f, 0.f, 0.f};
            const uint32_t* ah_base = Ahi + (wid * NKT) * 128 + lan * 4;
            const uint32_t* al_base = Alo + (wid * NKT) * 128 + lan * 4;
#pragma unroll 5
            for (int kt = 0; kt < NKT; kt++) {
                uint4 ah4 = *reinterpret_cast<const uint4*>(ah_base + kt * 128);
                uint4 al4 = *reinterpret_cast<const uint4*>(al_base + kt * 128);
                uint32_t ah[4] = {ah4.x, ah4.y, ah4.z, ah4.w};
                uint32_t al[4] = {al4.x, al4.y, al4.z, al4.w};
                uint2 b0h = *reinterpret_cast<const uint2*>(Bhi + (kt * 2 + 0) * 64 + lan * 2);
                uint2 b1h = *reinterpret_cast<const uint2*>(Bhi + (kt * 2 + 1) * 64 + lan * 2);
                uint2 b0l = *reinterpret_cast<const uint2*>(Blo + (kt * 2 + 0) * 64 + lan * 2);
                uint2 b1l = *reinterpret_cast<const uint2*>(Blo + (kt * 2 + 1) * 64 + lan * 2);
                uint32_t bh0[2] = {b0h.x, b0h.y}, bh1[2] = {b1h.x, b1h.y};
                uint32_t bl0[2] = {b0l.x, b0l.y}, bl1[2] = {b1l.x, b1l.y};
                mma16816(acc0, ah, bh0);
                mma16816(acc0, ah, bl0);
                mma16816(acc0, al, bh0);
                mma16816(acc1, ah, bh1);
                mma16816(acc1, ah, bl1);
                mma16816(acc1, al, bh1);
            }
            // park z (D frag layout -> z[m][b])
            int m0 = 16 * wid + (lan >> 2), b0 = 2 * (lan & 3);
            *reinterpret_cast<float2*>(&zb[(m0    ) * 18 + b0    ]) = make_float2(acc0[0], acc0[1]);
            *reinterpret_cast<float2*>(&zb[(m0 + 8) * 18 + b0    ]) = make_float2(acc0[2], acc0[3]);
            *reinterpret_cast<float2*>(&zb[(m0    ) * 18 + b0 + 8]) = make_float2(acc1[0], acc1[1]);
            *reinterpret_cast<float2*>(&zb[(m0 + 8) * 18 + b0 + 8]) = make_float2(acc1[2], acc1[3]);
        }
        __syncthreads();   // z ready

        // ---- pointwise LSTM: (j0, j0+1) x batch bq ----
        {
            float h01[2];
#pragma unroll
            for (int d = 0; d < 2; d++) {
                int mrow = 2 * jp + d;
                float zi = zb[(0 * 32 + mrow) * 18 + bq] + bz[0 + d];
                float zf = zb[(1 * 32 + mrow) * 18 + bq] + bz[2 + d];
                float zg = zb[(2 * 32 + mrow) * 18 + bq] + bz[4 + d];
                float zo = zb[(3 * 32 + mrow) * 18 + bq] + bz[6 + d];
                float cv = sigm(zf) * cst[d] + sigm(zi) * tanh_fast(zg);
                cst[d] = cv;
                h01[d] = sigm(zo) * tanh_fast(cv);
            }
            uint32_t lo, hi = split_pack(h01[0], h01[1], lo);
            __stcg(&g_hfrag[(t + 1) & 1][q][0][hwi], hi);
            __stcg(&g_hfrag[(t + 1) & 1][q][1][hwi], lo);
            if (t == TT - 1) {
                __stcg(&g_hT[(q * BC + bq) * HH + j0], h01[0]);
                __stcg(&g_hT[(q * BC + bq) * HH + j0 + 1], h01[1]);
            }
        }
        // prefetch x(t+1)
        if (t + 1 < TT) {
            pva = *reinterpret_cast<const float2*>(xrow + (size_t)(t + 1) * DD + xd0);
            pvb = *reinterpret_cast<const float2*>(xrow + (size_t)(t + 1) * DD + xd0 + 8);
        }
        CLU_ARRIVE();   // release h(t)
    }
    CLU_WAIT();

    // ---- output head: CTA handles batches {2r, 2r+1}; 20 tasks over 8 warps ----
    for (int task = wid; task < 2 * NCLASS; task += 8) {
        int row = task / NCLASS, cls = task % NCLASS;
        int b = q * BC + 2 * r + row;
        float s = 0.0f;
#pragma unroll
        for (int k = lan; k < HH; k += 32)
            s += __ldcg(&g_hT[b * HH + k]) * Wout[cls * HH + k];
#pragma unroll
        for (int o = 16; o; o >>= 1) s += __shfl_xor_sync(0xffffffffu, s, o);
        if (lan == 0) out[b * NCLASS + cls] = sigm(s + bout[cls]);
    }
}

extern "C" void kernel_launch(void* const* d_in, const int* in_sizes, int n_in,
                              void* d_out, int out_size) {
    const float* x    = (const float*)d_in[0];
    const float* Wih  = (const float*)d_in[1];
    const float* Whh  = (const float*)d_in[2];
    const float* bih  = (const float*)d_in[3];
    const float* bhh  = (const float*)d_in[4];
    const float* Wout = (const float*)d_in[5];
    const float* bout = (const float*)d_in[6];
    float* out = (float*)d_out;

    cudaFuncSetAttribute(lstm_kernel,
                         cudaFuncAttributeMaxDynamicSharedMemorySize, SM_TOTAL);

    lstm_kernel<<<NC * CS, RTH, SM_TOTAL>>>(x, Wih, Whh, bih, bhh,
                                            Wout, bout, out);
}

// round 10
// speedup vs baseline: 2.4076x; 1.0853x over previous
#include <cuda_runtime.h>
#include <cuda_fp16.h>
#include <cstdint>
#include <cstddef>

// Problem sizes
#define HH     256
#define BB     256
#define TT     512
#define DD     64
#define NCLASS 10

// Topology: 16 clusters x 8 CTAs; cluster owns 16 batch rows; CTA owns 32 j.
#define CS   8
#define NC   16
#define BC   16
#define RTH  512   // 16 warps: warp = (mt = w&7, kh = w>>3)
#define NKT  20    // k-tiles: 16 for H=256, 4 for D=64
#define KHT  10    // k-tiles per k-half warp

// ---- SMEM layout (bytes) ----
// A-lo frags: [8 mt][20 kt][32 lanes][4 u32] = 81920
// B frags:    [20 kt][2 nt][32 lanes][2 u32] = 10240 each (hi, lo)
// z partials: [128 m][18 floats] = 9216 each (z0, z1)
#define SM_AL  0
#define SM_BHI (SM_AL + 8 * NKT * 512)
#define SM_BLO (SM_BHI + NKT * 2 * 256)
#define SM_Z0  (SM_BLO + NKT * 2 * 256)
#define SM_Z1  (SM_Z0 + 128 * 18 * 4)
#define SM_TOTAL (SM_Z1 + 128 * 18 * 4)   // 120832

// h exchange: B-fragment-layout image, words 0..2047 (16 h k-tiles), per parity.
__device__ uint32_t g_hfrag[2][NC][2][2048];   // [parity][cluster][hi/lo][word]
__device__ float g_hT[BB * HH];

// ---------------------------------------------------------------------------
__device__ __forceinline__ float sigm(float x) { return 1.0f / (1.0f + __expf(-x)); }
__device__ __forceinline__ float tanh_fast(float x) {
    return 1.0f - 2.0f / (__expf(2.0f * x) + 1.0f);
}
__device__ __forceinline__ uint32_t split_pack(float a, float b, uint32_t& lo) {
    __half ah = __float2half_rn(a), bh = __float2half_rn(b);
    __half al = __float2half_rn(a - __half2float(ah));
    __half bl = __float2half_rn(b - __half2float(bh));
    __half2 h2 = __halves2half2(ah, bh), l2 = __halves2half2(al, bl);
    lo = *reinterpret_cast<uint32_t*>(&l2);
    return *reinterpret_cast<uint32_t*>(&h2);
}
__device__ __forceinline__ void mma16816(float* d, const uint32_t* a, const uint32_t* b) {
    asm volatile(
        "mma.sync.aligned.m16n8k16.row.col.f32.f16.f16.f32 "
        "{%0,%1,%2,%3}, {%4,%5,%6,%7}, {%8,%9}, {%0,%1,%2,%3};"
        : "+f"(d[0]), "+f"(d[1]), "+f"(d[2]), "+f"(d[3])
        : "r"(a[0]), "r"(a[1]), "r"(a[2]), "r"(a[3]), "r"(b[0]), "r"(b[1]));
}
#define CLU_ARRIVE() asm volatile("barrier.cluster.arrive.aligned;" ::: "memory")
#define CLU_WAIT()   asm volatile("barrier.cluster.wait.aligned;"   ::: "memory")

// ---------------------------------------------------------------------------
// Fragment layouts identical to R9 (verified):
//  A row-major m16n8k16: lane l, reg j: row = 16*mt + (l>>2) + 8*(j&1),
//                        col = 16*kt + 2*(l&3) + 8*(j>>1)
//  B: word (kt*2+nt)*64 + l*2 + j : k = 16*kt + 2*(l&3) + 8*j, n = nt*8 + (l>>2)
//  D: lane l: rows 16*mt + (l>>2) (+8), cols 2*(l&3) (+1)
// A rows: m = gate*32 + jl; k<256 -> Whh, else Wih.
// ---------------------------------------------------------------------------
__global__ __launch_bounds__(RTH, 1) __cluster_dims__(CS, 1, 1)
void lstm_kernel(const float* __restrict__ x,
                 const float* __restrict__ Wih,
                 const float* __restrict__ Whh,
                 const float* __restrict__ bih,
                 const float* __restrict__ bhh,
                 const float* __restrict__ Wout,
                 const float* __restrict__ bout,
                 float* __restrict__ out) {
    extern __shared__ __align__(16) char smc[];
    const int tid = threadIdx.x;
    const int wid = tid >> 5, lan = tid & 31;
    const int mt = wid & 7, kh = wid >> 3;
    const int kt0 = kh * KHT;
    const int cta = blockIdx.x, q = cta / CS, r = cta % CS;

    uint32_t* Al  = reinterpret_cast<uint32_t*>(smc + SM_AL);
    uint32_t* Bhi = reinterpret_cast<uint32_t*>(smc + SM_BHI);
    uint32_t* Blo = reinterpret_cast<uint32_t*>(smc + SM_BLO);
    float*    z0  = reinterpret_cast<float*>(smc + SM_Z0);
    float*    z1  = reinterpret_cast<float*>(smc + SM_Z1);
    float*    zmy = kh ? z1 : z0;

    // ---- zero parity-0 h image (h0 = 0) ----
    if (tid < 128)
        reinterpret_cast<uint4*>(&g_hfrag[0][q][0][0])[r * 128 + tid] =
            make_uint4(0u, 0u, 0u, 0u);

    // ---- build A fragments: hi -> registers (persistent), lo -> smem ----
    uint32_t Ah[KHT][4];
#pragma unroll
    for (int ktl = 0; ktl < KHT; ktl++) {
        int kt = kt0 + ktl;
#pragma unroll
        for (int reg = 0; reg < 4; reg++) {
            int m  = 16 * mt + (lan >> 2) + 8 * (reg & 1);
            int kk = 16 * kt + 2 * (lan & 3) + 8 * (reg >> 1);
            int row = (m >> 5) * HH + r * 32 + (m & 31);   // gate*256 + j
            float2 v;
            if (kk < HH)
                v = *reinterpret_cast<const float2*>(&Whh[(size_t)row * HH + kk]);
            else
                v = *reinterpret_cast<const float2*>(&Wih[(size_t)row * DD + (kk - HH)]);
            uint32_t lo, hi = split_pack(v.x, v.y, lo);
            Ah[ktl][reg] = hi;
            Al[(mt * NKT + kt) * 128 + lan * 4 + reg] = lo;
        }
    }

    // ---- pointwise constants (threads 0..255 own (jp, bq); tp keeps addrs safe) ----
    const int tp = tid & 255;
    const int jp = tp >> 4, bq = tp & 15;
    const int j0 = r * 32 + 2 * jp;
    float bz[8];
#pragma unroll
    for (int g = 0; g < 4; g++) {
        bz[2 * g + 0] = bih[g * HH + j0] + bhh[g * HH + j0];
        bz[2 * g + 1] = bih[g * HH + j0 + 1] + bhh[g * HH + j0 + 1];
    }
    // h-writer fragment word index for (j0, j0+1) x batch bq
    const int wkt = 2 * r + (jp >> 3);
    const int wnt = bq >> 3;
    const int wl  = (bq & 7) * 4 + (jp & 3);
    const int wreg = (jp >> 2) & 1;
    const int hwi = (wkt * 2 + wnt) * 64 + wl * 2 + wreg;

    // ---- x-frag ownership (threads 0..255): words w0 = 2048 + 2*tp, +1 ----
    const int w0  = 2048 + 2 * tp;
    const int xkt = w0 >> 7;                 // 16..19
    const int xr2 = w0 & 127;
    const int xnt = xr2 >> 6;
    const int xl  = (xr2 >> 1) & 31;
    const int xn  = xnt * 8 + (xl >> 2);
    const int xd0 = (xkt - 16) * 16 + 2 * (xl & 3);
    const float* xrow = x + ((size_t)(q * BC + xn) * TT) * DD;
    float2 pva = make_float2(0.f, 0.f), pvb = make_float2(0.f, 0.f);
    if (tid < 256) {
        pva = *reinterpret_cast<const float2*>(xrow + xd0);
        pvb = *reinterpret_cast<const float2*>(xrow + xd0 + 8);
    }

    float cst[2] = {0.f, 0.f};

    __syncthreads();
    CLU_ARRIVE();   // publish zeroed h image

    for (int t = 0; t < TT; t++) {
        CLU_WAIT();   // peers' h(t-1) frags visible; all MMA reads of t-1 done

        // ---- ingest h frags (1024 uint4 over 512 threads) ----
        {
            const uint4* ghi = reinterpret_cast<const uint4*>(&g_hfrag[t & 1][q][0][0]);
            const uint4* glo = reinterpret_cast<const uint4*>(&g_hfrag[t & 1][q][1][0]);
            reinterpret_cast<uint4*>(Bhi)[tid] = __ldcg(ghi + tid);
            reinterpret_cast<uint4*>(Blo)[tid] = __ldcg(glo + tid);
        }
        // ---- x frags from prefetched regs ----
        if (tid < 256) {
            uint32_t lo0, hi0 = split_pack(pva.x, pva.y, lo0);
            uint32_t lo1, hi1 = split_pack(pvb.x, pvb.y, lo1);
            *reinterpret_cast<uint2*>(Bhi + w0) = make_uint2(hi0, hi1);
            *reinterpret_cast<uint2*>(Blo + w0) = make_uint2(lo0, lo1);
        }
        __syncthreads();   // fragments ready

        // ---- MMA: warp (mt, kh): 10 kt x 2 nt x 3 passes; A-hi from regs ----
        {
            float acc0[4] = {0.f, 0.f, 0.f, 0.f};
            float acc1[4] = {0.f, 0.f, 0.f, 0.f};
            const uint32_t* al_base = Al + (mt * NKT + kt0) * 128 + lan * 4;
#pragma unroll
            for (int ktl = 0; ktl < KHT; ktl++) {
                int kt = kt0 + ktl;
                uint4 al4 = *reinterpret_cast<const uint4*>(al_base + ktl * 128);
                uint32_t al[4] = {al4.x, al4.y, al4.z, al4.w};
                uint2 b0h = *reinterpret_cast<const uint2*>(Bhi + (kt * 2 + 0) * 64 + lan * 2);
                uint2 b1h = *reinterpret_cast<const uint2*>(Bhi + (kt * 2 + 1) * 64 + lan * 2);
                uint2 b0l = *reinterpret_cast<const uint2*>(Blo + (kt * 2 + 0) * 64 + lan * 2);
                uint2 b1l = *reinterpret_cast<const uint2*>(Blo + (kt * 2 + 1) * 64 + lan * 2);
                uint32_t bh0[2] = {b0h.x, b0h.y}, bh1[2] = {b1h.x, b1h.y};
                uint32_t bl0[2] = {b0l.x, b0l.y}, bl1[2] = {b1l.x, b1l.y};
                mma16816(acc0, Ah[ktl], bh0);
                mma16816(acc0, Ah[ktl], bl0);
                mma16816(acc0, al, bh0);
                mma16816(acc1, Ah[ktl], bh1);
                mma16816(acc1, Ah[ktl], bl1);
                mma16816(acc1, al, bh1);
            }
            // park partial z in this k-half's buffer (D frag layout -> z[m][b])
            int m0 = 16 * mt + (lan >> 2), b0 = 2 * (lan & 3);
            *reinterpret_cast<float2*>(&zmy[(m0    ) * 18 + b0    ]) = make_float2(acc0[0], acc0[1]);
            *reinterpret_cast<float2*>(&zmy[(m0 + 8) * 18 + b0    ]) = make_float2(acc0[2], acc0[3]);
            *reinterpret_cast<float2*>(&zmy[(m0    ) * 18 + b0 + 8]) = make_float2(acc1[0], acc1[1]);
            *reinterpret_cast<float2*>(&zmy[(m0 + 8) * 18 + b0 + 8]) = make_float2(acc1[2], acc1[3]);
        }
        __syncthreads();   // z0 + z1 ready

        // ---- pointwise LSTM: (j0, j0+1) x batch bq (threads 0..255) ----
        if (tid < 256) {
            float h01[2];
#pragma unroll
            for (int d = 0; d < 2; d++) {
                int mrow = 2 * jp + d;
                float zi = z0[(0 * 32 + mrow) * 18 + bq] + z1[(0 * 32 + mrow) * 18 + bq] + bz[0 + d];
                float zf = z0[(1 * 32 + mrow) * 18 + bq] + z1[(1 * 32 + mrow) * 18 + bq] + bz[2 + d];
                float zg = z0[(2 * 32 + mrow) * 18 + bq] + z1[(2 * 32 + mrow) * 18 + bq] + bz[4 + d];
                float zo = z0[(3 * 32 + mrow) * 18 + bq] + z1[(3 * 32 + mrow) * 18 + bq] + bz[6 + d];
                float cv = sigm(zf) * cst[d] + sigm(zi) * tanh_fast(zg);
                cst[d] = cv;
                h01[d] = sigm(zo) * tanh_fast(cv);
            }
            uint32_t lo, hi = split_pack(h01[0], h01[1], lo);
            __stcg(&g_hfrag[(t + 1) & 1][q][0][hwi], hi);
            __stcg(&g_hfrag[(t + 1) & 1][q][1][hwi], lo);
            if (t == TT - 1) {
                __stcg(&g_hT[(q * BC + bq) * HH + j0], h01[0]);
                __stcg(&g_hT[(q * BC + bq) * HH + j0 + 1], h01[1]);
            }
            // prefetch x(t+1)
            if (t + 1 < TT) {
                pva = *reinterpret_cast<const float2*>(xrow + (size_t)(t + 1) * DD + xd0);
                pvb = *reinterpret_cast<const float2*>(xrow + (size_t)(t + 1) * DD + xd0 + 8);
            }
        }
        CLU_ARRIVE();   // release h(t)
    }
    CLU_WAIT();

    // ---- output head: CTA handles batches {2r, 2r+1}; 20 tasks / 16 warps ----
    for (int task = wid; task < 2 * NCLASS; task += 16) {
        int row = task / NCLASS, cls = task % NCLASS;
        int b = q * BC + 2 * r + row;
        float s = 0.0f;
#pragma unroll
        for (int k = lan; k < HH; k += 32)
            s += __ldcg(&g_hT[b * HH + k]) * Wout[cls * HH + k];
#pragma unroll
        for (int o = 16; o; o >>= 1) s += __shfl_xor_sync(0xffffffffu, s, o);
        if (lan == 0) out[b * NCLASS + cls] = sigm(s + bout[cls]);
    }
}

extern "C" void kernel_launch(void* const* d_in, const int* in_sizes, int n_in,
                              void* d_out, int out_size) {
    const float* x    = (const float*)d_in[0];
    const float* Wih  = (const float*)d_in[1];
    const float* Whh  = (const float*)d_in[2];
    const float* bih  = (const float*)d_in[3];
    const float* bhh  = (const float*)d_in[4];
    const float* Wout = (const float*)d_in[5];
    const float* bout = (const float*)d_in[6];
    float* out = (float*)d_out;

    cudaFuncSetAttribute(lstm_kernel,
                         cudaFuncAttributeMaxDynamicSharedMemorySize, SM_TOTAL);

    lstm_kernel<<<NC * CS, RTH, SM_TOTAL>>>(x, Wih, Whh, bih, bhh,
                                            Wout, bout, out);
}

// round 12
// speedup vs baseline: 2.4487x; 1.0171x over previous
#include <cuda_runtime.h>
#include <cuda_fp16.h>
#include <cstdint>
#include <cstddef>

// Problem sizes
#define HH     256
#define BB     256
#define TT     512
#define DD     64
#define NCLASS 10

// Topology: 16 clusters x 8 CTAs; cluster owns 16 batch rows; CTA owns 32 j.
#define CS   8
#define NC   16
#define BC   16
#define RTH  512   // 16 warps: warp = (mt = w&7, kh = w>>3)
#define NKT  20    // k-tiles: 16 for H=256 (kt 0..15), 4 for D=64 (kt 16..19)
#define KHT  10    // k-tiles per k-half warp (interleaved: kt = kh + 2*ktl)

// ---- SMEM layout (bytes) ----
// A-lo frags: [8 mt][20 kt][32 lanes][4 u32] = 81920
// x frags:    [2 bufs][512 words] hi + lo     = 4096 each
// z partials: [128 m][18 floats]              = 9216 each
#define SM_AL  0
#define SM_XHI (SM_AL + 8 * NKT * 512)
#define SM_XLO (SM_XHI + 2 * 512 * 4)
#define SM_Z0  (SM_XLO + 2 * 512 * 4)
#define SM_Z1  (SM_Z0 + 128 * 18 * 4)
#define SM_TOTAL (SM_Z1 + 128 * 18 * 4)   // 108544

// h exchange: B-fragment-layout image, words 0..2047 (16 h k-tiles), per parity.
// Word (kt*2+nt)*64 + l*2 + j : k = 16*kt + 2*(l&3) + 8*j (packed k,k+1),
//                               n = nt*8 + (l>>2)
__device__ uint32_t g_hfrag[2][NC][2][2048];   // [parity][cluster][hi/lo][word]
__device__ float g_hT[BB * HH];

// ---------------------------------------------------------------------------
__device__ __forceinline__ float sigm(float x) { return 1.0f / (1.0f + __expf(-x)); }
__device__ __forceinline__ float tanh_fast(float x) {
    return 1.0f - 2.0f / (__expf(2.0f * x) + 1.0f);
}
__device__ __forceinline__ uint32_t split_pack(float a, float b, uint32_t& lo) {
    __half ah = __float2half_rn(a), bh = __float2half_rn(b);
    __half al = __float2half_rn(a - __half2float(ah));
    __half bl = __float2half_rn(b - __half2float(bh));
    __half2 h2 = __halves2half2(ah, bh), l2 = __halves2half2(al, bl);
    lo = *reinterpret_cast<uint32_t*>(&l2);
    return *reinterpret_cast<uint32_t*>(&h2);
}
__device__ __forceinline__ void mma16816(float* d, const uint32_t* a, const uint32_t* b) {
    asm volatile(
        "mma.sync.aligned.m16n8k16.row.col.f32.f16.f16.f32 "
        "{%0,%1,%2,%3}, {%4,%5,%6,%7}, {%8,%9}, {%0,%1,%2,%3};"
        : "+f"(d[0]), "+f"(d[1]), "+f"(d[2]), "+f"(d[3])
        : "r"(a[0]), "r"(a[1]), "r"(a[2]), "r"(a[3]), "r"(b[0]), "r"(b[1]));
}
// 6 MMAs of a Karatsuba k-tile (hi*hi + hi*lo + lo*hi) for both n-tiles.
// Plain inline function: no macro-shadowing hazards.
__device__ __forceinline__ void mma6(float* acc0, float* acc1,
                                     const uint32_t* a_hi, const uint32_t* a_lo,
                                     uint2 vh0, uint2 vl0, uint2 vh1, uint2 vl1) {
    uint32_t ph0[2] = {vh0.x, vh0.y};
    uint32_t pl0[2] = {vl0.x, vl0.y};
    uint32_t ph1[2] = {vh1.x, vh1.y};
    uint32_t pl1[2] = {vl1.x, vl1.y};
    mma16816(acc0, a_hi, ph0);
    mma16816(acc0, a_hi, pl0);
    mma16816(acc0, a_lo, ph0);
    mma16816(acc1, a_hi, ph1);
    mma16816(acc1, a_hi, pl1);
    mma16816(acc1, a_lo, ph1);
}
#define CLU_ARRIVE() asm volatile("barrier.cluster.arrive.aligned;" ::: "memory")
#define CLU_WAIT()   asm volatile("barrier.cluster.wait.aligned;"   ::: "memory")

// ---------------------------------------------------------------------------
// Fragment layouts identical to R9/R10 (verified):
//  A row-major m16n8k16: lane l, reg j: row = 16*mt + (l>>2) + 8*(j&1),
//                        col = 16*kt + 2*(l&3) + 8*(j>>1)
//  D: lane l: rows 16*mt + (l>>2) (+8), cols 2*(l&3) (+1)
// A rows: m = gate*32 + jl; k<256 -> Whh, else Wih (x part).
// ---------------------------------------------------------------------------
__global__ __launch_bounds__(RTH, 1) __cluster_dims__(CS, 1, 1)
void lstm_kernel(const float* __restrict__ x,
                 const float* __restrict__ Wih,
                 const float* __restrict__ Whh,
                 const float* __restrict__ bih,
                 const float* __restrict__ bhh,
                 const float* __restrict__ Wout,
                 const float* __restrict__ bout,
                 float* __restrict__ out) {
    extern __shared__ __align__(16) char smc[];
    const int tid = threadIdx.x;
    const int wid = tid >> 5, lan = tid & 31;
    const int mt = wid & 7, kh = wid >> 3;
    const int cta = blockIdx.x, q = cta / CS, r = cta % CS;

    uint32_t* Al  = reinterpret_cast<uint32_t*>(smc + SM_AL);
    uint32_t* Xhi = reinterpret_cast<uint32_t*>(smc + SM_XHI);
    uint32_t* Xlo = reinterpret_cast<uint32_t*>(smc + SM_XLO);
    float*    z0  = reinterpret_cast<float*>(smc + SM_Z0);
    float*    z1  = reinterpret_cast<float*>(smc + SM_Z1);
    float*    zmy = kh ? z1 : z0;

    // ---- zero parity-0 h image (h0 = 0) ----
    if (tid < 128)
        reinterpret_cast<uint4*>(&g_hfrag[0][q][0][0])[r * 128 + tid] =
            make_uint4(0u, 0u, 0u, 0u);

    // ---- build A fragments: hi -> registers (interleaved kts), lo -> smem ----
    uint32_t Ah[KHT][4];
#pragma unroll
    for (int ktl = 0; ktl < KHT; ktl++) {
        int kt = kh + 2 * ktl;
#pragma unroll
        for (int reg = 0; reg < 4; reg++) {
            int m  = 16 * mt + (lan >> 2) + 8 * (reg & 1);
            int kk = 16 * kt + 2 * (lan & 3) + 8 * (reg >> 1);
            int row = (m >> 5) * HH + r * 32 + (m & 31);   // gate*256 + j
            float2 v;
            if (kk < HH)
                v = *reinterpret_cast<const float2*>(&Whh[(size_t)row * HH + kk]);
            else
                v = *reinterpret_cast<const float2*>(&Wih[(size_t)row * DD + (kk - HH)]);
            uint32_t lo, hi = split_pack(v.x, v.y, lo);
            Ah[ktl][reg] = hi;
            Al[(mt * NKT + kt) * 128 + lan * 4 + reg] = lo;
        }
    }

    // ---- pointwise constants (threads 0..255 own (jp, bq)) ----
    const int tp = tid & 255;
    const int jp = tp >> 4, bq = tp & 15;
    const int j0 = r * 32 + 2 * jp;
    float bz[8];
#pragma unroll
    for (int g = 0; g < 4; g++) {
        bz[2 * g + 0] = bih[g * HH + j0] + bhh[g * HH + j0];
        bz[2 * g + 1] = bih[g * HH + j0 + 1] + bhh[g * HH + j0 + 1];
    }
    // h-writer fragment word index for (j0, j0+1) x batch bq
    const int wkt = 2 * r + (jp >> 3);
    const int wnt = bq >> 3;
    const int wl  = (bq & 7) * 4 + (jp & 3);
    const int wreg = (jp >> 2) & 1;
    const int hwi = (wkt * 2 + wnt) * 64 + wl * 2 + wreg;

    // ---- x-frag ownership (threads 0..255): words {2*tp, 2*tp+1} of 512 ----
    const int xktn = tp >> 5;                 // (kt16)*2 + nt, 0..7
    const int xln  = tp & 31;
    const int xn   = (xktn & 1) * 8 + (xln >> 2);
    const int xd0  = (xktn >> 1) * 16 + 2 * (xln & 3);
    const float* xrow = x + ((size_t)(q * BC + xn) * TT) * DD;
    float2 pva = make_float2(0.f, 0.f), pvb = make_float2(0.f, 0.f);
    if (tid < 256) {
        // publish x(0) into buffer 0 directly
        float2 va = *reinterpret_cast<const float2*>(xrow + xd0);
        float2 vb = *reinterpret_cast<const float2*>(xrow + xd0 + 8);
        uint32_t lo0, hi0 = split_pack(va.x, va.y, lo0);
        uint32_t lo1, hi1 = split_pack(vb.x, vb.y, lo1);
        *reinterpret_cast<uint2*>(Xhi + 2 * tp) = make_uint2(hi0, hi1);
        *reinterpret_cast<uint2*>(Xlo + 2 * tp) = make_uint2(lo0, lo1);
        // prefetch x(1)
        pva = *reinterpret_cast<const float2*>(xrow + DD + xd0);
        pvb = *reinterpret_cast<const float2*>(xrow + DD + xd0 + 8);
    }

    float cst[2] = {0.f, 0.f};

    __syncthreads();
    CLU_ARRIVE();   // publish zeroed h image

    for (int t = 0; t < TT; t++) {
        float acc0[4] = {0.f, 0.f, 0.f, 0.f};
        float acc1[4] = {0.f, 0.f, 0.f, 0.f};

        // ---- x-part MMAs (local; hides cluster barrier skew) ----
        {
            const uint32_t* xh = Xhi + (t & 1) * 512;
            const uint32_t* xl = Xlo + (t & 1) * 512;
#pragma unroll
            for (int ktl = 8; ktl < 10; ktl++) {
                int kt = kh + 2 * ktl;                       // 16..19
                int tb = ((kt - 16) * 2) * 64 + lan * 2;
                uint2 bh0 = *reinterpret_cast<const uint2*>(xh + tb);
                uint2 bh1 = *reinterpret_cast<const uint2*>(xh + tb + 64);
                uint2 bl0 = *reinterpret_cast<const uint2*>(xl + tb);
                uint2 bl1 = *reinterpret_cast<const uint2*>(xl + tb + 64);
                uint4 al4 = *reinterpret_cast<const uint4*>(
                    Al + (mt * NKT + kt) * 128 + lan * 4);
                uint32_t alr[4] = {al4.x, al4.y, al4.z, al4.w};
                mma6(acc0, acc1, Ah[ktl], alr, bh0, bl0, bh1, bl1);
            }
        }

        CLU_WAIT();   // peers' h(t-1) frags visible

        // ---- h-part MMAs: B frags straight from global (no smem staging) ----
        {
            const uint32_t* ghi = &g_hfrag[t & 1][q][0][0];
            const uint32_t* glo = &g_hfrag[t & 1][q][1][0];
#pragma unroll
            for (int ktl = 0; ktl < 8; ktl++) {
                int kt = kh + 2 * ktl;
                int tb = (kt * 2) * 64 + lan * 2;
                uint2 bh0 = __ldcg(reinterpret_cast<const uint2*>(ghi + tb));
                uint2 bh1 = __ldcg(reinterpret_cast<const uint2*>(ghi + tb + 64));
                uint2 bl0 = __ldcg(reinterpret_cast<const uint2*>(glo + tb));
                uint2 bl1 = __ldcg(reinterpret_cast<const uint2*>(glo + tb + 64));
                uint4 al4 = *reinterpret_cast<const uint4*>(
                    Al + (mt * NKT + kt) * 128 + lan * 4);
                uint32_t alr[4] = {al4.x, al4.y, al4.z, al4.w};
                mma6(acc0, acc1, Ah[ktl], alr, bh0, bl0, bh1, bl1);
            }
        }

        // ---- park partial z (D frag layout -> z[m][b]) ----
        {
            int m0 = 16 * mt + (lan >> 2), b0 = 2 * (lan & 3);
            *reinterpret_cast<float2*>(&zmy[(m0    ) * 18 + b0    ]) = make_float2(acc0[0], acc0[1]);
            *reinterpret_cast<float2*>(&zmy[(m0 + 8) * 18 + b0    ]) = make_float2(acc0[2], acc0[3]);
            *reinterpret_cast<float2*>(&zmy[(m0    ) * 18 + b0 + 8]) = make_float2(acc1[0], acc1[1]);
            *reinterpret_cast<float2*>(&zmy[(m0 + 8) * 18 + b0 + 8]) = make_float2(acc1[2], acc1[3]);
        }
        // publish x(t+1) frags into the other buffer (before the sync)
        if (tid < 256 && t + 1 < TT) {
            uint32_t lo0, hi0 = split_pack(pva.x, pva.y, lo0);
            uint32_t lo1, hi1 = split_pack(pvb.x, pvb.y, lo1);
            uint32_t* xh = Xhi + ((t + 1) & 1) * 512;
            uint32_t* xl = Xlo + ((t + 1) & 1) * 512;
            *reinterpret_cast<uint2*>(xh + 2 * tp) = make_uint2(hi0, hi1);
            *reinterpret_cast<uint2*>(xl + 2 * tp) = make_uint2(lo0, lo1);
        }
        __syncthreads();   // z0+z1 + x(t+1) frags ready

        // ---- pointwise LSTM: (j0, j0+1) x batch bq (threads 0..255) ----
        if (tid < 256) {
            float h01[2];
#pragma unroll
            for (int d = 0; d < 2; d++) {
                int mrow = 2 * jp + d;
                float zi = z0[(0 * 32 + mrow) * 18 + bq] + z1[(0 * 32 + mrow) * 18 + bq] + bz[0 + d];
                float zf = z0[(1 * 32 + mrow) * 18 + bq] + z1[(1 * 32 + mrow) * 18 + bq] + bz[2 + d];
                float zg = z0[(2 * 32 + mrow) * 18 + bq] + z1[(2 * 32 + mrow) * 18 + bq] + bz[4 + d];
                float zo = z0[(3 * 32 + mrow) * 18 + bq] + z1[(3 * 32 + mrow) * 18 + bq] + bz[6 + d];
                float cv = sigm(zf) * cst[d] + sigm(zi) * tanh_fast(zg);
                cst[d] = cv;
                h01[d] = sigm(zo) * tanh_fast(cv);
            }
            uint32_t lo, hi = split_pack(h01[0], h01[1], lo);
            __stcg(&g_hfrag[(t + 1) & 1][q][0][hwi], hi);
            __stcg(&g_hfrag[(t + 1) & 1][q][1][hwi], lo);
            if (t == TT - 1) {
                __stcg(&g_hT[(q * BC + bq) * HH + j0], h01[0]);
                __stcg(&g_hT[(q * BC + bq) * HH + j0 + 1], h01[1]);
            }
            // prefetch x(t+2)
            if (t + 2 < TT) {
                pva = *reinterpret_cast<const float2*>(xrow + (size_t)(t + 2) * DD + xd0);
                pvb = *reinterpret_cast<const float2*>(xrow + (size_t)(t + 2) * DD + xd0 + 8);
            }
        }
        CLU_ARRIVE();   // release h(t)
    }
    CLU_WAIT();

    // ---- output head: CTA handles batches {2r, 2r+1}; 20 tasks / 16 warps ----
    for (int task = wid; task < 2 * NCLASS; task += 16) {
        int row = task / NCLASS, cls = task % NCLASS;
        int b = q * BC + 2 * r + row;
        float s = 0.0f;
#pragma unroll
        for (int k = lan; k < HH; k += 32)
            s += __ldcg(&g_hT[b * HH + k]) * Wout[cls * HH + k];
#pragma unroll
        for (int o = 16; o; o >>= 1) s += __shfl_xor_sync(0xffffffffu, s, o);
        if (lan == 0) out[b * NCLASS + cls] = sigm(s + bout[cls]);
    }
}

extern "C" void kernel_launch(void* const* d_in, const int* in_sizes, int n_in,
                              void* d_out, int out_size) {
    const float* x    = (const float*)d_in[0];
    const float* Wih  = (const float*)d_in[1];
    const float* Whh  = (const float*)d_in[2];
    const float* bih  = (const float*)d_in[3];
    const float* bhh  = (const float*)d_in[4];
    const float* Wout = (const float*)d_in[5];
    const float* bout = (const float*)d_in[6];
    float* out = (float*)d_out;

    cudaFuncSetAttribute(lstm_kernel,
                         cudaFuncAttributeMaxDynamicSharedMemorySize, SM_TOTAL);

    lstm_kernel<<<NC * CS, RTH, SM_TOTAL>>>(x, Wih, Whh, bih, bhh,
                                            Wout, bout, out);
}